// round 7
// baseline (speedup 1.0000x reference)
#include <cuda_runtime.h>

#define D        128
#define K_EMB    1024
#define BM       64
#define BK       16
#define NTHREADS 256
#define SEPAD    132            // Es row stride in floats (33 float4s -> conflict-free reads)

__device__ float g_enorm[K_EMB];
__device__ float g_partial[512];

// ---------------- kernel 1: ||e||^2 per embedding ----------------
__global__ void vq_enorm_kernel(const float* __restrict__ emb) {
    int w    = (blockIdx.x * blockDim.x + threadIdx.x) >> 5;
    int lane = threadIdx.x & 31;
    if (w >= K_EMB) return;
    float4 v = ((const float4*)emb)[w * 32 + lane];
    float s = v.x * v.x + v.y * v.y + v.z * v.z + v.w * v.w;
    #pragma unroll
    for (int o = 16; o > 0; o >>= 1) s += __shfl_xor_sync(0xffffffffu, s, o);
    if (lane == 0) g_enorm[w] = s;
}

// ---------------- kernel 2: scores + argmin + gather + loss partial ----------------
__global__ __launch_bounds__(NTHREADS)
void vq_main_kernel(const float* __restrict__ x, const float* __restrict__ emb,
                    float* __restrict__ out) {
    __shared__ float Xs[BM * D];          // 32768 B   (row-major, broadcast reads)
    __shared__ float Es[BK * SEPAD];      //  8448 B   (padded; reused as reduction scratch)
    __shared__ float ens[K_EMB];          //  4096 B
    __shared__ int   sIdx[BM];            //   256 B
    __shared__ float lossp[8];

    const int t    = threadIdx.x;
    const int tx   = t & 15;              // column within tile
    const int ty   = t >> 4;              // row group
    const int row0 = blockIdx.x * BM;

    // ||e||^2 table
    #pragma unroll
    for (int i = 0; i < K_EMB / NTHREADS; ++i)
        ens[t + i * NTHREADS] = g_enorm[t + i * NTHREADS];

    // X tile: coalesced float4, row-major
    {
        const float4* xg = (const float4*)(x + (size_t)row0 * D);
        float4*       xs = (float4*)Xs;
        #pragma unroll
        for (int it = 0; it < BM * D / 4 / NTHREADS; ++it) {
            int flat = t + it * NTHREADS;
            xs[flat] = xg[flat];
        }
    }

    float bestS[4];
    int   bestI[4];
    #pragma unroll
    for (int i = 0; i < 4; ++i) { bestS[i] = 3.4e38f; bestI[i] = 0; }

    for (int tile = 0; tile < K_EMB / BK; ++tile) {
        __syncthreads();
        // E tile: 16 codes x 128 floats into padded rows (warp writes one row)
        {
            const float4* eg = (const float4*)(emb + (size_t)tile * BK * D);
            #pragma unroll
            for (int it = 0; it < BK * D / 4 / NTHREADS; ++it) {
                int flat = t + it * NTHREADS;
                int r = flat >> 5, c = flat & 31;
                *(float4*)&Es[r * SEPAD + 4 * c] = eg[r * 32 + c];
            }
        }
        __syncthreads();

        float acc[4] = {0.f, 0.f, 0.f, 0.f};
        const float4* es4 = (const float4*)&Es[tx * SEPAD];
        #pragma unroll 4
        for (int d4 = 0; d4 < D / 4; ++d4) {
            float4 e4 = es4[d4];
            #pragma unroll
            for (int i = 0; i < 4; ++i) {
                float4 x4 = *(const float4*)&Xs[(ty + 16 * i) * D + 4 * d4];
                acc[i] = fmaf(x4.x, e4.x, acc[i]);
                acc[i] = fmaf(x4.y, e4.y, acc[i]);
                acc[i] = fmaf(x4.z, e4.z, acc[i]);
                acc[i] = fmaf(x4.w, e4.w, acc[i]);
            }
        }

        int kg = tile * BK + tx;
        float half_en = 0.5f * ens[kg];
        #pragma unroll
        for (int i = 0; i < 4; ++i) {
            float s = half_en - acc[i];            // argmin(0.5||e||^2 - x.e) == argmin dist^2
            if (s < bestS[i]) { bestS[i] = s; bestI[i] = kg; }
        }
    }

    // ---- cross-thread argmin (overlay Es region: 2048 of 2112 floats) ----
    float* sS = Es;                     // [BM*16]
    int*   sI = (int*)(Es + BM * 16);   // [BM*16]
    __syncthreads();
    #pragma unroll
    for (int i = 0; i < 4; ++i) {
        int r = ty + 16 * i;
        sS[r * 16 + tx] = bestS[i];
        sI[r * 16 + tx] = bestI[i];
    }
    __syncthreads();
    if (t < BM) {
        float bs = sS[t * 16];
        int   bi = sI[t * 16];
        #pragma unroll
        for (int q = 1; q < 16; ++q) {
            float s  = sS[t * 16 + q];
            int   ii = sI[t * 16 + q];
            if (s < bs || (s == bs && ii < bi)) { bs = s; bi = ii; }
        }
        sIdx[t] = bi;
    }
    __syncthreads();

    // ---- q gather (coalesced) + loss partial ----
    int w = t >> 5, lane = t & 31;
    float lsum = 0.f;
    #pragma unroll
    for (int rr = 0; rr < BM / 8; ++rr) {
        int r  = w * (BM / 8) + rr;
        int bi = sIdx[r];
        float4 e4 = ((const float4*)emb)[bi * 32 + lane];
        float4 x4 = *(const float4*)&Xs[r * D + 4 * lane];
        float dx = e4.x - x4.x, dy = e4.y - x4.y, dz = e4.z - x4.z, dw = e4.w - x4.w;
        lsum += dx * dx + dy * dy + dz * dz + dw * dw;
        ((float4*)out)[(size_t)(row0 + r) * 32 + lane] = e4;
    }
    #pragma unroll
    for (int o = 16; o > 0; o >>= 1) lsum += __shfl_xor_sync(0xffffffffu, lsum, o);
    if (lane == 0) lossp[w] = lsum;
    __syncthreads();
    if (t == 0) {
        float s = 0.f;
        #pragma unroll
        for (int w2 = 0; w2 < 8; ++w2) s += lossp[w2];
        g_partial[blockIdx.x] = s;
    }
}

// ---------------- kernel 3: deterministic loss finalize ----------------
__global__ void vq_loss_finalize(float* __restrict__ out, int nblocks, long long pos) {
    __shared__ float s[NTHREADS];
    int t = threadIdx.x;
    float acc = 0.f;
    for (int i = t; i < nblocks; i += NTHREADS) acc += g_partial[i];
    s[t] = acc;
    __syncthreads();
    #pragma unroll
    for (int o = NTHREADS / 2; o > 0; o >>= 1) {
        if (t < o) s[t] += s[t + o];
        __syncthreads();
    }
    if (t == 0) out[pos] = 1.5f * s[0];  // codebook + BETA*commitment = 1.5 * sum((q-x)^2)
}

// ---------------- launch ----------------
extern "C" void kernel_launch(void* const* d_in, const int* in_sizes, int n_in,
                              void* d_out, int out_size) {
    const float* x = (const float*)d_in[0];
    const float* e = (const float*)d_in[1];
    int nx = in_sizes[0];
    if (n_in >= 2 && in_sizes[0] == K_EMB * D && in_sizes[1] != K_EMB * D) {
        const float* tmp = x; x = e; e = tmp;
        nx = in_sizes[1];
    }
    int N = nx / D;                  // 32768
    int nblocks = N / BM;            // 512

    vq_enorm_kernel<<<K_EMB / 8, NTHREADS>>>(e);
    vq_main_kernel<<<nblocks, NTHREADS>>>(x, e, (float*)d_out);
    if (out_size > N * D) {
        vq_loss_finalize<<<1, NTHREADS>>>((float*)d_out, nblocks, (long long)N * D);
    }
}